// round 3
// baseline (speedup 1.0000x reference)
#include <cuda_runtime.h>
#include <stdint.h>

#define D 128
#define MAX_N 50048

// Scratch (device globals — no allocation allowed). All fully rewritten each launch.
__device__ float g_h[(size_t)MAX_N * D];
__device__ float g_dis[MAX_N];
__device__ int   g_deg[MAX_N];

// ---------------- degree ----------------
__global__ void k_deg_init(int n) {
    int i = blockIdx.x * blockDim.x + threadIdx.x;
    if (i < n) g_deg[i] = 1;                    // self-loop
}

__global__ void k_deg_count(const int* __restrict__ ei, int e) {
    int i = blockIdx.x * blockDim.x + threadIdx.x;
    if (i < e) atomicAdd(&g_deg[ei[e + i]], 1);   // dst row of edge_index (int32!)
}

__global__ void k_dis(int n) {
    int i = blockIdx.x * blockDim.x + threadIdx.x;
    if (i < n) g_dis[i] = rsqrtf((float)g_deg[i]);             // deg >= 1 always
}

// ---------------- GEMM h = x@W, fused self-loop epilogue ----------------
// block = 256 threads (8 warps), 64 rows/block, warp handles 8 rows,
// lane computes 4 contiguous output cols. W k-slice loaded once per k (L1-hot),
// reused across 8 rows -> FFMA-bound.
__global__ __launch_bounds__(256) void k_gemm(const float* __restrict__ x,
                                              const float* __restrict__ W,
                                              const float* __restrict__ b,
                                              float* __restrict__ out, int n) {
    __shared__ float xs[64][D];
    int row0 = blockIdx.x * 64;

    // cooperative load of 64 input rows (float4)
    for (int i = threadIdx.x; i < 64 * (D / 4); i += blockDim.x) {
        int r = i >> 5;            // 32 float4 per row
        int c = (i & 31) << 2;
        int gr = row0 + r;
        float4 v = make_float4(0.f, 0.f, 0.f, 0.f);
        if (gr < n) v = *(const float4*)(x + (size_t)gr * D + c);
        *(float4*)&xs[r][c] = v;
    }
    __syncthreads();

    int warp = threadIdx.x >> 5;
    int lane = threadIdx.x & 31;
    int c = lane << 2;

    float4 acc[8];
#pragma unroll
    for (int r = 0; r < 8; r++) acc[r] = make_float4(0.f, 0.f, 0.f, 0.f);

#pragma unroll 4
    for (int k = 0; k < D; k++) {
        float4 wk = *(const float4*)(W + k * D + c);
#pragma unroll
        for (int r = 0; r < 8; r++) {
            float xv = xs[warp * 8 + r][k];
            acc[r].x += xv * wk.x;
            acc[r].y += xv * wk.y;
            acc[r].z += xv * wk.z;
            acc[r].w += xv * wk.w;
        }
    }

    float4 bv = *(const float4*)(b + c);
#pragma unroll
    for (int r = 0; r < 8; r++) {
        int gr = row0 + warp * 8 + r;
        if (gr < n) {
            *(float4*)(g_h + (size_t)gr * D + c) = acc[r];
            float di = g_dis[gr];
            float s = di * di;                       // self-loop norm
            float4 o;
            o.x = acc[r].x * s + bv.x;
            o.y = acc[r].y * s + bv.y;
            o.z = acc[r].z * s + bv.z;
            o.w = acc[r].w * s + bv.w;
            *(float4*)(out + (size_t)gr * D + c) = o;
        }
    }
}

// ---------------- edge scatter: warp per edge, vector reduction ----------------
__global__ __launch_bounds__(256) void k_edge(const int* __restrict__ ei,
                                              float* __restrict__ out, int e) {
    int w = (blockIdx.x * blockDim.x + threadIdx.x) >> 5;
    int lane = threadIdx.x & 31;
    if (w >= e) return;
    int s = ei[w];          // src
    int d = ei[e + w];      // dst
    float norm = g_dis[s] * g_dis[d];
    float4 h = *(const float4*)(g_h + (size_t)s * D + (lane << 2));
    h.x *= norm; h.y *= norm; h.z *= norm; h.w *= norm;
    float* p = out + (size_t)d * D + (lane << 2);
    asm volatile("red.global.add.v4.f32 [%0], {%1,%2,%3,%4};"
                 :: "l"(p), "f"(h.x), "f"(h.y), "f"(h.z), "f"(h.w)
                 : "memory");
}

extern "C" void kernel_launch(void* const* d_in, const int* in_sizes, int n_in,
                              void* d_out, int out_size) {
    const float* x  = (const float*)d_in[0];
    const int*   ei = (const int*)d_in[1];     // edge_index is int32 (JAX x64 disabled)
    const float* W  = (const float*)d_in[2];
    const float* b  = (const float*)d_in[3];
    float* out = (float*)d_out;

    int n = in_sizes[0] / D;
    int e = in_sizes[1] / 2;

    k_deg_init<<<(n + 255) / 256, 256>>>(n);
    k_deg_count<<<(e + 255) / 256, 256>>>(ei, e);
    k_dis<<<(n + 255) / 256, 256>>>(n);
    k_gemm<<<(n + 63) / 64, 256>>>(x, W, b, out, n);
    k_edge<<<(e + 7) / 8, 256>>>(ei, out, e);
}

// round 4
// speedup vs baseline: 1.1170x; 1.1170x over previous
#include <cuda_runtime.h>
#include <stdint.h>

#define D 128
#define MAX_N 50048

// Scratch (device globals — no allocation allowed). All fully rewritten each launch.
__device__ float g_h[(size_t)MAX_N * D];   // h' = (x@W) * dis[row]  (pre-scaled by src norm)
__device__ float g_dis[MAX_N];
__device__ int   g_deg[MAX_N];

typedef unsigned long long u64;

// ---- packed fp32x2 helpers (Blackwell f32x2 pipe, PTX-only) ----
__device__ __forceinline__ void fma2(u64 &acc, u64 a, u64 b) {
    asm("fma.rn.f32x2 %0, %1, %2, %0;" : "+l"(acc) : "l"(a), "l"(b));
}
__device__ __forceinline__ u64 pack2(float v) {
    u64 r; asm("mov.b64 %0, {%1, %1};" : "=l"(r) : "f"(v)); return r;
}
__device__ __forceinline__ u64 packxy(float x, float y) {
    u64 r; asm("mov.b64 %0, {%1, %2};" : "=l"(r) : "f"(x), "f"(y)); return r;
}
__device__ __forceinline__ float2 unpack2(u64 v) {
    float2 f; asm("mov.b64 {%0, %1}, %2;" : "=f"(f.x), "=f"(f.y) : "l"(v)); return f;
}

// ---------------- degree ----------------
__global__ void k_deg_init(int n) {
    int i = blockIdx.x * blockDim.x + threadIdx.x;
    if (i < n) g_deg[i] = 1;                    // self-loop
}

__global__ void k_deg_count(const int* __restrict__ ei, int e) {
    int i = blockIdx.x * blockDim.x + threadIdx.x;
    if (i < e) atomicAdd(&g_deg[ei[e + i]], 1);   // dst row (edge_index is int32)
}

__global__ void k_dis(int n) {
    int i = blockIdx.x * blockDim.x + threadIdx.x;
    if (i < n) g_dis[i] = rsqrtf((float)g_deg[i]);  // deg >= 1 always
}

// ---------------- GEMM h = x@W via packed f32x2 FMA, fused epilogue ----------------
// 256 thr, 64 rows/block, warp = 8 rows, lane = 4 contiguous cols.
// Inner loop: k in chunks of 4; W rows via LDG.128 (L1-resident, 64KB),
// xs via LDS.128, accumulate with fma.rn.f32x2 (2 MACs/inst -> fma-pipe floor halves).
__global__ __launch_bounds__(256) void k_gemm(const float* __restrict__ x,
                                              const float* __restrict__ W,
                                              const float* __restrict__ b,
                                              float* __restrict__ out, int n) {
    __shared__ float xs[64][D];
    int row0 = blockIdx.x * 64;

    for (int i = threadIdx.x; i < 64 * (D / 4); i += 256) {
        int r = i >> 5;
        int c4 = (i & 31) << 2;
        int gr = row0 + r;
        float4 v = make_float4(0.f, 0.f, 0.f, 0.f);
        if (gr < n) v = *(const float4*)(x + (size_t)gr * D + c4);
        *(float4*)&xs[r][c4] = v;
    }
    __syncthreads();

    int warp = threadIdx.x >> 5;
    int lane = threadIdx.x & 31;
    int c = lane << 2;

    u64 acc[8][2];
#pragma unroll
    for (int r = 0; r < 8; r++) { acc[r][0] = 0ULL; acc[r][1] = 0ULL; }

#pragma unroll 2
    for (int k = 0; k < D; k += 4) {
        u64 w0[2], w1[2], w2[2], w3[2];
        {
            float4 t;
            t = *(const float4*)(W + (k + 0) * D + c); w0[0] = packxy(t.x, t.y); w0[1] = packxy(t.z, t.w);
            t = *(const float4*)(W + (k + 1) * D + c); w1[0] = packxy(t.x, t.y); w1[1] = packxy(t.z, t.w);
            t = *(const float4*)(W + (k + 2) * D + c); w2[0] = packxy(t.x, t.y); w2[1] = packxy(t.z, t.w);
            t = *(const float4*)(W + (k + 3) * D + c); w3[0] = packxy(t.x, t.y); w3[1] = packxy(t.z, t.w);
        }
#pragma unroll
        for (int r = 0; r < 8; r++) {
            float4 xv = *(const float4*)&xs[warp * 8 + r][k];
            u64 xx;
            xx = pack2(xv.x); fma2(acc[r][0], xx, w0[0]); fma2(acc[r][1], xx, w0[1]);
            xx = pack2(xv.y); fma2(acc[r][0], xx, w1[0]); fma2(acc[r][1], xx, w1[1]);
            xx = pack2(xv.z); fma2(acc[r][0], xx, w2[0]); fma2(acc[r][1], xx, w2[1]);
            xx = pack2(xv.w); fma2(acc[r][0], xx, w3[0]); fma2(acc[r][1], xx, w3[1]);
        }
    }

    float4 bv = *(const float4*)(b + c);
#pragma unroll
    for (int r = 0; r < 8; r++) {
        int gr = row0 + warp * 8 + r;
        if (gr < n) {
            float di = g_dis[gr];
            float2 lo = unpack2(acc[r][0]);
            float2 hi = unpack2(acc[r][1]);
            float4 hp;                                  // h' = h * dis[row]
            hp.x = lo.x * di; hp.y = lo.y * di;
            hp.z = hi.x * di; hp.w = hi.y * di;
            *(float4*)(g_h + (size_t)gr * D + c) = hp;
            float4 o;                                   // self-loop: h*dis^2 + b = h'*dis + b
            o.x = hp.x * di + bv.x;
            o.y = hp.y * di + bv.y;
            o.z = hp.z * di + bv.z;
            o.w = hp.w * di + bv.w;
            *(float4*)(out + (size_t)gr * D + c) = o;
        }
    }
}

// ---------------- edge scatter: warp per edge, vector reduction ----------------
// msg = h'[src] * dis[dst]   (h' already carries dis[src])
__global__ __launch_bounds__(256) void k_edge(const int* __restrict__ ei,
                                              float* __restrict__ out, int e) {
    int w = (blockIdx.x * blockDim.x + threadIdx.x) >> 5;
    int lane = threadIdx.x & 31;
    if (w >= e) return;
    int s = ei[w];          // src
    int d = ei[e + w];      // dst
    float nd = g_dis[d];
    float4 h = *(const float4*)(g_h + (size_t)s * D + (lane << 2));
    h.x *= nd; h.y *= nd; h.z *= nd; h.w *= nd;
    float* p = out + (size_t)d * D + (lane << 2);
    asm volatile("red.global.add.v4.f32 [%0], {%1,%2,%3,%4};"
                 :: "l"(p), "f"(h.x), "f"(h.y), "f"(h.z), "f"(h.w)
                 : "memory");
}

extern "C" void kernel_launch(void* const* d_in, const int* in_sizes, int n_in,
                              void* d_out, int out_size) {
    const float* x  = (const float*)d_in[0];
    const int*   ei = (const int*)d_in[1];     // edge_index int32 (JAX x64 disabled)
    const float* W  = (const float*)d_in[2];
    const float* b  = (const float*)d_in[3];
    float* out = (float*)d_out;

    int n = in_sizes[0] / D;
    int e = in_sizes[1] / 2;

    k_deg_init<<<(n + 255) / 256, 256>>>(n);
    k_deg_count<<<(e + 255) / 256, 256>>>(ei, e);
    k_dis<<<(n + 255) / 256, 256>>>(n);
    k_gemm<<<(n + 63) / 64, 256>>>(x, W, b, out, n);
    k_edge<<<(e + 7) / 8, 256>>>(ei, out, e);
}